// round 1
// baseline (speedup 1.0000x reference)
#include <cuda_runtime.h>

#define NND 50000
#define NE  800000
#define HID 128
#define OUTC 2

#define BM  64
#define LDA 132   // padded shared stride for A tile (528B rows, 16B aligned)

// ---------------- device scratch (no allocations allowed) ----------------
__device__ int   g_deg[NND];
__device__ int   g_rowptr[NND + 1];
__device__ int   g_cursor[NND];
__device__ int   g_col[NE];
__device__ float g_bufA[(size_t)NND * HID];
__device__ float g_bufB[(size_t)NND * HID];
__device__ int   g_is64;

// ---------------- edge dtype detection (int64 vs int32) ----------------
__global__ void k_detect(const long long* __restrict__ ei) {
    if (blockIdx.x == 0 && threadIdx.x == 0) {
        unsigned long long h = 0;
        for (int i = 0; i < 64; i++)
            h |= ((unsigned long long)ei[i]) >> 32;
        // true int64 node ids < 2^31 have zero high words; int32 data packs two
        // random ids per 64-bit word so some high word is nonzero.
        g_is64 = (h == 0ull) ? 1 : 0;
    }
}

// ---------------- CSR build ----------------
__global__ void k_zero_deg() {
    int i = blockIdx.x * blockDim.x + threadIdx.x;
    if (i < NND) g_deg[i] = 0;
}

__global__ void k_hist(const void* __restrict__ ei) {
    int e = blockIdx.x * blockDim.x + threadIdx.x;
    if (e >= NE) return;
    int d;
    if (g_is64) d = (int)reinterpret_cast<const long long*>(ei)[NE + e];
    else        d = reinterpret_cast<const int*>(ei)[NE + e];
    atomicAdd(&g_deg[d], 1);
}

// single-block exclusive scan over 50000 degrees
__global__ void k_scan() {
    __shared__ int tsum[1024];
    const int CH = (NND + 1023) / 1024;  // 49
    int t = threadIdx.x;
    int start = t * CH;
    int s = 0;
    for (int i = 0; i < CH; i++) {
        int idx = start + i;
        if (idx < NND) s += g_deg[idx];
    }
    tsum[t] = s;
    __syncthreads();
    for (int off = 1; off < 1024; off <<= 1) {
        int v = (t >= off) ? tsum[t - off] : 0;
        __syncthreads();
        tsum[t] += v;
        __syncthreads();
    }
    int run = (t == 0) ? 0 : tsum[t - 1];
    for (int i = 0; i < CH; i++) {
        int idx = start + i;
        if (idx < NND) {
            g_rowptr[idx] = run;
            g_cursor[idx] = run;
            run += g_deg[idx];
        }
    }
    if (t == 0) g_rowptr[NND] = NE;
}

__global__ void k_fill(const void* __restrict__ ei) {
    int e = blockIdx.x * blockDim.x + threadIdx.x;
    if (e >= NE) return;
    int s, d;
    if (g_is64) {
        s = (int)reinterpret_cast<const long long*>(ei)[e];
        d = (int)reinterpret_cast<const long long*>(ei)[NE + e];
    } else {
        s = reinterpret_cast<const int*>(ei)[e];
        d = reinterpret_cast<const int*>(ei)[NE + e];
    }
    int pos = atomicAdd(&g_cursor[d], 1);
    g_col[pos] = s;
}

// ---------------- aggregation: out[i] = in[i] + sum_{j in N(i)} in[j] ----------------
// one warp per node, float4 per lane (lane covers channels 4*lane..4*lane+3)
__global__ void k_gather(const float4* __restrict__ in4, float4* __restrict__ out4) {
    int node = (int)((blockIdx.x * blockDim.x + threadIdx.x) >> 5);
    if (node >= NND) return;
    int lane = threadIdx.x & 31;
    float4 acc = in4[(size_t)node * 32 + lane];
    int beg = g_rowptr[node], end = g_rowptr[node + 1];
    for (int k = beg; k < end; k++) {
        int j = g_col[k];
        float4 v = in4[(size_t)j * 32 + lane];
        acc.x += v.x; acc.y += v.y; acc.z += v.z; acc.w += v.w;
    }
    out4[(size_t)node * 32 + lane] = acc;
}

// ---------------- fused 2-layer MLP with f32x2 packed FMA ----------------
// computes: out = maybe_relu( relu(A @ Wa + ba) @ Wb + bb ), A: [NND,128]
__device__ __forceinline__ void gemm_tile(const float* __restrict__ As,
                                          const float* __restrict__ Ws,
                                          int TX, int TY, float t[4][8]) {
    unsigned long long acc[4][4];
#pragma unroll
    for (int r = 0; r < 4; r++)
#pragma unroll
        for (int i = 0; i < 4; i++) acc[r][i] = 0ull;

#pragma unroll 4
    for (int k = 0; k < HID; k++) {
        ulonglong2 b01 = *reinterpret_cast<const ulonglong2*>(Ws + k * HID + TX * 8);
        ulonglong2 b23 = *reinterpret_cast<const ulonglong2*>(Ws + k * HID + TX * 8 + 4);
        unsigned long long bv0 = b01.x, bv1 = b01.y, bv2 = b23.x, bv3 = b23.y;
#pragma unroll
        for (int r = 0; r < 4; r++) {
            float a = As[(TY * 4 + r) * LDA + k];
            unsigned long long av;
            asm("mov.b64 %0, {%1, %1};" : "=l"(av) : "f"(a));
            asm("fma.rn.f32x2 %0, %1, %2, %0;" : "+l"(acc[r][0]) : "l"(av), "l"(bv0));
            asm("fma.rn.f32x2 %0, %1, %2, %0;" : "+l"(acc[r][1]) : "l"(av), "l"(bv1));
            asm("fma.rn.f32x2 %0, %1, %2, %0;" : "+l"(acc[r][2]) : "l"(av), "l"(bv2));
            asm("fma.rn.f32x2 %0, %1, %2, %0;" : "+l"(acc[r][3]) : "l"(av), "l"(bv3));
        }
    }
#pragma unroll
    for (int r = 0; r < 4; r++)
#pragma unroll
        for (int i = 0; i < 4; i++) {
            float lo, hi;
            asm("mov.b64 {%0, %1}, %2;" : "=f"(lo), "=f"(hi) : "l"(acc[r][i]));
            t[r][2 * i] = lo;
            t[r][2 * i + 1] = hi;
        }
}

__global__ void __launch_bounds__(256, 2) k_mlp(
    const float* __restrict__ A,
    const float* __restrict__ Wa, const float* __restrict__ ba,
    const float* __restrict__ Wb, const float* __restrict__ bb,
    float* __restrict__ out, int final_relu) {
    extern __shared__ float sm[];
    float* As = sm;                 // BM x LDA
    float* Ws = sm + BM * LDA;      // 128 x 128
    const int tid = threadIdx.x;
    const int TX = tid & 15;        // column group: cols TX*8 .. TX*8+7
    const int TY = tid >> 4;        // row group:    rows TY*4 .. TY*4+3
    const int m_base = blockIdx.x * BM;

    // load A tile (BM x 128), zero-pad beyond NND
#pragma unroll
    for (int i = 0; i < 8; i++) {
        int idx = i * 256 + tid;           // float4 index over 64*32
        int r = idx >> 5, cv = idx & 31;
        int m = m_base + r;
        float4 v = make_float4(0.f, 0.f, 0.f, 0.f);
        if (m < NND) v = *reinterpret_cast<const float4*>(A + (size_t)m * HID + cv * 4);
        *reinterpret_cast<float4*>(As + r * LDA + cv * 4) = v;
    }
    // load Wa (128 x 128)
#pragma unroll
    for (int i = 0; i < 16; i++) {
        int idx = i * 256 + tid;
        *reinterpret_cast<float4*>(Ws + idx * 4) =
            *reinterpret_cast<const float4*>(Wa + idx * 4);
    }
    __syncthreads();

    float t[4][8];
    gemm_tile(As, Ws, TX, TY, t);

    float bias[8];
#pragma unroll
    for (int c = 0; c < 8; c++) bias[c] = ba[TX * 8 + c];
#pragma unroll
    for (int r = 0; r < 4; r++)
#pragma unroll
        for (int c = 0; c < 8; c++) {
            float v = t[r][c] + bias[c];
            t[r][c] = v > 0.f ? v : 0.f;   // inner ReLU
        }

    __syncthreads();  // everyone done reading As/Ws

    // store intermediate into As, load Wb into Ws
#pragma unroll
    for (int r = 0; r < 4; r++) {
        float* p = As + (TY * 4 + r) * LDA + TX * 8;
        *reinterpret_cast<float4*>(p)     = make_float4(t[r][0], t[r][1], t[r][2], t[r][3]);
        *reinterpret_cast<float4*>(p + 4) = make_float4(t[r][4], t[r][5], t[r][6], t[r][7]);
    }
#pragma unroll
    for (int i = 0; i < 16; i++) {
        int idx = i * 256 + tid;
        *reinterpret_cast<float4*>(Ws + idx * 4) =
            *reinterpret_cast<const float4*>(Wb + idx * 4);
    }
    __syncthreads();

    gemm_tile(As, Ws, TX, TY, t);

#pragma unroll
    for (int c = 0; c < 8; c++) bias[c] = bb[TX * 8 + c];
#pragma unroll
    for (int r = 0; r < 4; r++) {
        int m = m_base + TY * 4 + r;
        if (m >= NND) continue;
#pragma unroll
        for (int c = 0; c < 8; c++) {
            float v = t[r][c] + bias[c];
            if (final_relu) v = v > 0.f ? v : 0.f;
            t[r][c] = v;
        }
        float* p = out + (size_t)m * HID + TX * 8;
        *reinterpret_cast<float4*>(p)     = make_float4(t[r][0], t[r][1], t[r][2], t[r][3]);
        *reinterpret_cast<float4*>(p + 4) = make_float4(t[r][4], t[r][5], t[r][6], t[r][7]);
    }
}

// ---------------- FC head: out[n] = h[n] @ Wfc + bfc, OUTC=2 ----------------
__global__ void k_fc(const float* __restrict__ h, const float* __restrict__ Wfc,
                     const float* __restrict__ bfc, float* __restrict__ out) {
    int node = (int)((blockIdx.x * blockDim.x + threadIdx.x) >> 5);
    if (node >= NND) return;
    int lane = threadIdx.x & 31;
    float4 v = *reinterpret_cast<const float4*>(h + (size_t)node * HID + lane * 4);
    float p0 = 0.f, p1 = 0.f;
    const float* vv = reinterpret_cast<const float*>(&v);
#pragma unroll
    for (int j = 0; j < 4; j++) {
        int c = lane * 4 + j;
        p0 += vv[j] * Wfc[c * 2 + 0];
        p1 += vv[j] * Wfc[c * 2 + 1];
    }
#pragma unroll
    for (int off = 16; off; off >>= 1) {
        p0 += __shfl_down_sync(0xffffffff, p0, off);
        p1 += __shfl_down_sync(0xffffffff, p1, off);
    }
    if (lane == 0) {
        out[(size_t)node * 2 + 0] = p0 + bfc[0];
        out[(size_t)node * 2 + 1] = p1 + bfc[1];
    }
}

// ---------------- launch ----------------
extern "C" void kernel_launch(void* const* d_in, const int* in_sizes, int n_in,
                              void* d_out, int out_size) {
    const float* x   = (const float*)d_in[0];
    const void*  ei  = d_in[1];
    const float* W1a = (const float*)d_in[2];
    const float* b1a = (const float*)d_in[3];
    const float* W1b = (const float*)d_in[4];
    const float* b1b = (const float*)d_in[5];
    const float* W2a = (const float*)d_in[6];
    const float* b2a = (const float*)d_in[7];
    const float* W2b = (const float*)d_in[8];
    const float* b2b = (const float*)d_in[9];
    const float* Wfc = (const float*)d_in[10];
    const float* bfc = (const float*)d_in[11];
    float* out = (float*)d_out;

    void *pA = nullptr, *pB = nullptr;
    cudaGetSymbolAddress(&pA, g_bufA);
    cudaGetSymbolAddress(&pB, g_bufB);

    const int smem_bytes = (BM * LDA + HID * HID) * (int)sizeof(float);  // 99328
    cudaFuncSetAttribute(k_mlp, cudaFuncAttributeMaxDynamicSharedMemorySize, smem_bytes);

    const int GMLP = (NND + BM - 1) / BM;   // 782
    const int GW   = (NND + 7) / 8;         // 6250 blocks * 8 warps

    k_detect<<<1, 32>>>((const long long*)ei);
    k_zero_deg<<<(NND + 255) / 256, 256>>>();
    k_hist<<<NE / 256, 256>>>(ei);
    k_scan<<<1, 1024>>>();
    k_fill<<<NE / 256, 256>>>(ei);

    // layer 1
    k_gather<<<GW, 256>>>((const float4*)x, (float4*)pA);
    k_mlp<<<GMLP, 256, smem_bytes>>>((const float*)pA, W1a, b1a, W1b, b1b,
                                     (float*)pB, /*final_relu=*/1);
    // layer 2
    k_gather<<<GW, 256>>>((const float4*)pB, (float4*)pA);
    k_mlp<<<GMLP, 256, smem_bytes>>>((const float*)pA, W2a, b2a, W2b, b2b,
                                     (float*)pB, /*final_relu=*/0);
    // head
    k_fc<<<GW, 256>>>((const float*)pB, Wfc, bfc, out);
}

// round 2
// speedup vs baseline: 1.2618x; 1.2618x over previous
#include <cuda_runtime.h>

#define NND 50000
#define NE  800000
#define HID 128
#define OUTC 2

#define BM  64
#define LDA 132   // padded shared stride for A tile

#define SCB 256
#define NSB ((NND + SCB - 1) / SCB)   // 196 scan blocks

// ---------------- device scratch (no allocations allowed) ----------------
__device__ int   g_deg[NND];
__device__ int   g_rowptr[NND + 1];
__device__ int   g_cursor[NND];
__device__ int   g_col[NE];
__device__ int   g_part[NSB];
__device__ int   g_partoff[NSB];
__device__ float g_bufA[(size_t)NND * HID];
__device__ float g_bufB[(size_t)NND * HID];
__device__ int   g_is64;

// ---------------- edge dtype detection (int64 vs int32) ----------------
__global__ void k_detect(const long long* __restrict__ ei) {
    int lane = threadIdx.x & 31;
    unsigned long long h = ((unsigned long long)ei[lane]) >> 32;
    h |= ((unsigned long long)ei[lane + 32]) >> 32;
    unsigned any = __ballot_sync(0xffffffffu, h != 0ull);
    if (lane == 0) g_is64 = (any == 0u) ? 1 : 0;
}

// ---------------- CSR build ----------------
__global__ void k_zero_deg() {
    int i = blockIdx.x * blockDim.x + threadIdx.x;
    if (i < NND) g_deg[i] = 0;
}

__global__ void k_hist(const void* __restrict__ ei) {
    int e = blockIdx.x * blockDim.x + threadIdx.x;
    if (e >= NE) return;
    int d;
    if (g_is64) d = (int)reinterpret_cast<const long long*>(ei)[NE + e];
    else        d = reinterpret_cast<const int*>(ei)[NE + e];
    atomicAdd(&g_deg[d], 1);
}

// phase 1: per-block sums of 256 degrees
__global__ void k_s1() {
    int b = blockIdx.x, t = threadIdx.x;
    int idx = b * SCB + t;
    int v = (idx < NND) ? g_deg[idx] : 0;
#pragma unroll
    for (int o = 16; o; o >>= 1) v += __shfl_down_sync(0xffffffffu, v, o);
    __shared__ int ws[8];
    if ((t & 31) == 0) ws[t >> 5] = v;
    __syncthreads();
    if (t == 0) {
        int s = 0;
#pragma unroll
        for (int i = 0; i < 8; i++) s += ws[i];
        g_part[b] = s;
    }
}

// phase 2: exclusive scan of NSB (<=256) partials in one block
__global__ void k_s2() {
    int t = threadIdx.x;
    int lane = t & 31, w = t >> 5;
    int v = (t < NSB) ? g_part[t] : 0;
    int iv = v;
#pragma unroll
    for (int o = 1; o < 32; o <<= 1) {
        int u = __shfl_up_sync(0xffffffffu, iv, o);
        if (lane >= o) iv += u;
    }
    __shared__ int ws[8], wso[8];
    if (lane == 31) ws[w] = iv;
    __syncthreads();
    if (t == 0) {
        int run = 0;
#pragma unroll
        for (int i = 0; i < 8; i++) { wso[i] = run; run += ws[i]; }
        g_rowptr[NND] = NE;
    }
    __syncthreads();
    if (t < NSB) g_partoff[t] = wso[w] + iv - v;   // exclusive prefix
}

// phase 3: per-block local exclusive scan + global offset; write rowptr & cursor
__global__ void k_s3() {
    int b = blockIdx.x, t = threadIdx.x;
    int lane = t & 31, w = t >> 5;
    int idx = b * SCB + t;
    int v = (idx < NND) ? g_deg[idx] : 0;
    int iv = v;
#pragma unroll
    for (int o = 1; o < 32; o <<= 1) {
        int u = __shfl_up_sync(0xffffffffu, iv, o);
        if (lane >= o) iv += u;
    }
    __shared__ int ws[8], wso[8];
    if (lane == 31) ws[w] = iv;
    __syncthreads();
    if (t == 0) {
        int run = 0;
#pragma unroll
        for (int i = 0; i < 8; i++) { wso[i] = run; run += ws[i]; }
    }
    __syncthreads();
    int excl = g_partoff[b] + wso[w] + iv - v;
    if (idx < NND) {
        g_rowptr[idx] = excl;
        g_cursor[idx] = excl;
    }
}

__global__ void k_fill(const void* __restrict__ ei) {
    int e = blockIdx.x * blockDim.x + threadIdx.x;
    if (e >= NE) return;
    int s, d;
    if (g_is64) {
        s = (int)reinterpret_cast<const long long*>(ei)[e];
        d = (int)reinterpret_cast<const long long*>(ei)[NE + e];
    } else {
        s = reinterpret_cast<const int*>(ei)[e];
        d = reinterpret_cast<const int*>(ei)[NE + e];
    }
    int pos = atomicAdd(&g_cursor[d], 1);
    g_col[pos] = s;
}

// ---------------- aggregation: out[i] = in[i] + sum_{j in N(i)} in[j] ----------------
__global__ void k_gather(const float4* __restrict__ in4, float4* __restrict__ out4) {
    int node = (int)((blockIdx.x * blockDim.x + threadIdx.x) >> 5);
    if (node >= NND) return;
    int lane = threadIdx.x & 31;
    float4 acc = in4[(size_t)node * 32 + lane];
    int beg = g_rowptr[node], end = g_rowptr[node + 1];
    for (int k = beg; k < end; k++) {
        int j = g_col[k];
        float4 v = in4[(size_t)j * 32 + lane];
        acc.x += v.x; acc.y += v.y; acc.z += v.z; acc.w += v.w;
    }
    out4[(size_t)node * 32 + lane] = acc;
}

// ---------------- fused 2-layer MLP with f32x2 packed FMA ----------------
__device__ __forceinline__ void gemm_tile(const float* __restrict__ As,
                                          const float* __restrict__ Ws,
                                          int TX, int TY, float t[4][8]) {
    unsigned long long acc[4][4];
#pragma unroll
    for (int r = 0; r < 4; r++)
#pragma unroll
        for (int i = 0; i < 4; i++) acc[r][i] = 0ull;

#pragma unroll 4
    for (int k = 0; k < HID; k++) {
        ulonglong2 b01 = *reinterpret_cast<const ulonglong2*>(Ws + k * HID + TX * 8);
        ulonglong2 b23 = *reinterpret_cast<const ulonglong2*>(Ws + k * HID + TX * 8 + 4);
        unsigned long long bv0 = b01.x, bv1 = b01.y, bv2 = b23.x, bv3 = b23.y;
#pragma unroll
        for (int r = 0; r < 4; r++) {
            float a = As[(TY * 4 + r) * LDA + k];
            unsigned long long av;
            asm("mov.b64 %0, {%1, %1};" : "=l"(av) : "f"(a));
            asm("fma.rn.f32x2 %0, %1, %2, %0;" : "+l"(acc[r][0]) : "l"(av), "l"(bv0));
            asm("fma.rn.f32x2 %0, %1, %2, %0;" : "+l"(acc[r][1]) : "l"(av), "l"(bv1));
            asm("fma.rn.f32x2 %0, %1, %2, %0;" : "+l"(acc[r][2]) : "l"(av), "l"(bv2));
            asm("fma.rn.f32x2 %0, %1, %2, %0;" : "+l"(acc[r][3]) : "l"(av), "l"(bv3));
        }
    }
#pragma unroll
    for (int r = 0; r < 4; r++)
#pragma unroll
        for (int i = 0; i < 4; i++) {
            float lo, hi;
            asm("mov.b64 {%0, %1}, %2;" : "=f"(lo), "=f"(hi) : "l"(acc[r][i]));
            t[r][2 * i] = lo;
            t[r][2 * i + 1] = hi;
        }
}

// out layout: if Wfc==nullptr -> [NND,128] hidden with optional final relu;
// else -> [NND,2] fc head applied to (h @ Wb + bb) with no relu.
__global__ void __launch_bounds__(256, 2) k_mlp(
    const float* __restrict__ A,
    const float* __restrict__ Wa, const float* __restrict__ ba,
    const float* __restrict__ Wb, const float* __restrict__ bb,
    float* __restrict__ out, int final_relu,
    const float* __restrict__ Wfc, const float* __restrict__ bfc) {
    extern __shared__ float sm[];
    float* As = sm;                 // BM x LDA
    float* Ws = sm + BM * LDA;      // 128 x 128
    const int tid = threadIdx.x;
    const int TX = tid & 15;
    const int TY = tid >> 4;
    const int m_base = blockIdx.x * BM;

    // load A tile (BM x 128)
#pragma unroll
    for (int i = 0; i < 8; i++) {
        int idx = i * 256 + tid;
        int r = idx >> 5, cv = idx & 31;
        int m = m_base + r;
        float4 v = make_float4(0.f, 0.f, 0.f, 0.f);
        if (m < NND) v = *reinterpret_cast<const float4*>(A + (size_t)m * HID + cv * 4);
        *reinterpret_cast<float4*>(As + r * LDA + cv * 4) = v;
    }
#pragma unroll
    for (int i = 0; i < 16; i++) {
        int idx = i * 256 + tid;
        *reinterpret_cast<float4*>(Ws + idx * 4) =
            *reinterpret_cast<const float4*>(Wa + idx * 4);
    }
    __syncthreads();

    float t[4][8];
    gemm_tile(As, Ws, TX, TY, t);

    float bias[8];
#pragma unroll
    for (int c = 0; c < 8; c++) bias[c] = ba[TX * 8 + c];
#pragma unroll
    for (int r = 0; r < 4; r++)
#pragma unroll
        for (int c = 0; c < 8; c++) {
            float v = t[r][c] + bias[c];
            t[r][c] = v > 0.f ? v : 0.f;
        }

    __syncthreads();

#pragma unroll
    for (int r = 0; r < 4; r++) {
        float* p = As + (TY * 4 + r) * LDA + TX * 8;
        *reinterpret_cast<float4*>(p)     = make_float4(t[r][0], t[r][1], t[r][2], t[r][3]);
        *reinterpret_cast<float4*>(p + 4) = make_float4(t[r][4], t[r][5], t[r][6], t[r][7]);
    }
#pragma unroll
    for (int i = 0; i < 16; i++) {
        int idx = i * 256 + tid;
        *reinterpret_cast<float4*>(Ws + idx * 4) =
            *reinterpret_cast<const float4*>(Wb + idx * 4);
    }
    __syncthreads();

    gemm_tile(As, Ws, TX, TY, t);

#pragma unroll
    for (int c = 0; c < 8; c++) bias[c] = bb[TX * 8 + c];

    if (Wfc == nullptr) {
#pragma unroll
        for (int r = 0; r < 4; r++) {
            int m = m_base + TY * 4 + r;
            if (m >= NND) continue;
#pragma unroll
            for (int c = 0; c < 8; c++) {
                float v = t[r][c] + bias[c];
                if (final_relu) v = v > 0.f ? v : 0.f;
                t[r][c] = v;
            }
            float* p = out + (size_t)m * HID + TX * 8;
            *reinterpret_cast<float4*>(p)     = make_float4(t[r][0], t[r][1], t[r][2], t[r][3]);
            *reinterpret_cast<float4*>(p + 4) = make_float4(t[r][4], t[r][5], t[r][6], t[r][7]);
        }
    } else {
        // fused FC head: out[m, 0:2] = (h @ Wb + bb) @ Wfc + bfc
        float w0[8], w1[8];
#pragma unroll
        for (int c = 0; c < 8; c++) {
            int col = TX * 8 + c;
            w0[c] = Wfc[col * 2 + 0];
            w1[c] = Wfc[col * 2 + 1];
        }
        float bf0 = bfc[0], bf1 = bfc[1];
#pragma unroll
        for (int r = 0; r < 4; r++) {
            float s0 = 0.f, s1 = 0.f;
#pragma unroll
            for (int c = 0; c < 8; c++) {
                float v = t[r][c] + bias[c];
                s0 += v * w0[c];
                s1 += v * w1[c];
            }
#pragma unroll
            for (int o = 8; o; o >>= 1) {
                s0 += __shfl_down_sync(0xffffffffu, s0, o, 16);
                s1 += __shfl_down_sync(0xffffffffu, s1, o, 16);
            }
            int m = m_base + TY * 4 + r;
            if (TX == 0 && m < NND) {
                out[(size_t)m * 2 + 0] = s0 + bf0;
                out[(size_t)m * 2 + 1] = s1 + bf1;
            }
        }
    }
}

// ---------------- launch ----------------
extern "C" void kernel_launch(void* const* d_in, const int* in_sizes, int n_in,
                              void* d_out, int out_size) {
    const float* x   = (const float*)d_in[0];
    const void*  ei  = d_in[1];
    const float* W1a = (const float*)d_in[2];
    const float* b1a = (const float*)d_in[3];
    const float* W1b = (const float*)d_in[4];
    const float* b1b = (const float*)d_in[5];
    const float* W2a = (const float*)d_in[6];
    const float* b2a = (const float*)d_in[7];
    const float* W2b = (const float*)d_in[8];
    const float* b2b = (const float*)d_in[9];
    const float* Wfc = (const float*)d_in[10];
    const float* bfc = (const float*)d_in[11];
    float* out = (float*)d_out;

    void *pA = nullptr, *pB = nullptr;
    cudaGetSymbolAddress(&pA, g_bufA);
    cudaGetSymbolAddress(&pB, g_bufB);

    const int smem_bytes = (BM * LDA + HID * HID) * (int)sizeof(float);  // 99328
    cudaFuncSetAttribute(k_mlp, cudaFuncAttributeMaxDynamicSharedMemorySize, smem_bytes);

    const int GMLP = (NND + BM - 1) / BM;   // 782
    const int GW   = (NND + 7) / 8;         // warp-per-node grids

    k_detect<<<1, 32>>>((const long long*)ei);
    k_zero_deg<<<(NND + 255) / 256, 256>>>();
    k_hist<<<NE / 256, 256>>>(ei);
    k_s1<<<NSB, SCB>>>();
    k_s2<<<1, 256>>>();
    k_s3<<<NSB, SCB>>>();
    k_fill<<<NE / 256, 256>>>(ei);

    // layer 1
    k_gather<<<GW, 256>>>((const float4*)x, (float4*)pA);
    k_mlp<<<GMLP, 256, smem_bytes>>>((const float*)pA, W1a, b1a, W1b, b1b,
                                     (float*)pB, 1, nullptr, nullptr);
    // layer 2 + fused FC head
    k_gather<<<GW, 256>>>((const float4*)pB, (float4*)pA);
    k_mlp<<<GMLP, 256, smem_bytes>>>((const float*)pA, W2a, b2a, W2b, b2b,
                                     out, 0, Wfc, bfc);
}